// round 5
// baseline (speedup 1.0000x reference)
#include <cuda_runtime.h>

// Problem constants (fixed by the reference)
#define E    1024
#define NBLK 6
#define FF   4096
#define NWA  8
#define NWF  4
#define CC   1000
#define BB   4096
#define TPB  1024
#define PARTS 4                 // warps cooperating per GEMV output row
#define MAXCTA 256

// ---------------- device scratch (no allocations allowed) ----------------
__device__ float g_part[PARTS * E];       // partial dots (attn0 / f / classifier)
__device__ float g_M[NBLK * E * NWA];     // precomputed Wo@Wv  (E x 8 per block)
__device__ int   g_flags[MAXCTA * 32];    // barrier flags, 128B apart (zero-init)

// ---------------- reset-free flag grid barrier (all CTAs resident) -------
// Monotonic counters, never reset. At kernel entry all flags are equal
// (previous launch completed => every CTA did the same # of increments),
// so each CTA snapshots its OWN flag as the baseline. Barrier p waits for
// every peer flag >= base + p. Replay/graph safe by construction.
__device__ __forceinline__ void grid_sync(int nb, int b, int base, int phase) {
    __syncthreads();
    if (threadIdx.x == 0) {
        __threadfence();                                   // release our writes
        *((volatile int*)&g_flags[b * 32]) = base + phase; // own slot, sole writer
    }
    if (threadIdx.x < nb) {
        while (*((volatile int*)&g_flags[threadIdx.x * 32]) < base + phase) {}
    }
    __threadfence();                                       // acquire
    __syncthreads();
}

// Segment dot: this warp covers N4 float4 of a row (row & xs pre-offset).
template<int N4>
__device__ __forceinline__ float warp_dot_seg(const float4* __restrict__ row,
                                              const float4* __restrict__ xs, int lane) {
    float acc = 0.f;
#pragma unroll
    for (int k = 0; k < N4 / 32; k++) {
        float4 w = row[lane + 32 * k];
        float4 x = xs[lane + 32 * k];
        acc = fmaf(w.x, x.x, acc);
        acc = fmaf(w.y, x.y, acc);
        acc = fmaf(w.z, x.z, acc);
        acc = fmaf(w.w, x.w, acc);
    }
#pragma unroll
    for (int o = 16; o; o >>= 1) acc += __shfl_xor_sync(0xffffffffu, acc, o);
    return acc;
}

extern "C" __global__ void __launch_bounds__(TPB, 1)
hkt_kernel(const float* __restrict__ Wv,
           const float* __restrict__ Wo,
           const float* __restrict__ phi_q,
           const float* __restrict__ W1,
           const float* __restrict__ W2,
           const float* __restrict__ phi_f,
           const float* __restrict__ ln1_g, const float* __restrict__ ln1_b,
           const float* __restrict__ ln2_g, const float* __restrict__ ln2_b,
           const float* __restrict__ Wc,   const float* __restrict__ bc,
           float* __restrict__ out)
{
    __shared__ __align__(16) float h_s[E];
    __shared__ __align__(16) float v_s[E];
    __shared__ __align__(16) float r_s[FF];
    __shared__ float red1_s[32];
    __shared__ float red2_s[32];
    __shared__ float m_s[NWA];
    __shared__ float stats[2];
    __shared__ int   base_s;

    const int tid  = threadIdx.x;
    const int lane = tid & 31;
    const int wc   = tid >> 5;
    const int b    = blockIdx.x;
    const int nb   = gridDim.x;
    const int gw   = wc * nb + b;             // global warp id
    const int wstride = 32 * nb;
    int phase = 0;

    // snapshot own barrier flag as baseline (all flags equal at entry)
    if (tid == 0) base_s = *((volatile int*)&g_flags[b * 32]);

    // h0 = 1 + pe0 = [1,2,1,2,...]  (kern == 1 exactly; x is dead)
    h_s[tid] = 1.0f + (float)(tid & 1);
    __syncthreads();
    const int base = base_s;

    // ================== PHASE 1 (single grid phase, merged) ==================
    // (a) block-0 attn partials: v0 = Wv0 @ cos(h0[:8]+phi) local, then
    //     4-warps-per-row partial dots of Wo0 @ v0 into g_part.
    // (b) M_blk = Wo_blk @ Wv_blk for blk = 1..5 (data-independent).
    if (tid < NWA) m_s[tid] = cosf(h_s[tid] + phi_q[tid]);
    __syncthreads();
    {
        const float4* wv = (const float4*)(Wv + (size_t)tid * NWA);
        float4 a = wv[0], c = wv[1];
        v_s[tid] = a.x * m_s[0] + a.y * m_s[1] + a.z * m_s[2] + a.w * m_s[3]
                 + c.x * m_s[4] + c.y * m_s[5] + c.z * m_s[6] + c.w * m_s[7];
    }
    __syncthreads();
    {
        const float4* vv = (const float4*)v_s;
        const int n_attn = PARTS * E;                 // 4096
        const int n_tot  = n_attn + (NBLK - 1) * E;   // + 5120 M tasks
        for (int t = gw; t < n_tot; t += wstride) {
            if (t < n_attn) {
                int e = t >> 2, p = t & 3;
                const float4* row = (const float4*)Wo + (size_t)e * (E / 4) + p * (E / 4 / PARTS);
                float acc = warp_dot_seg<E / 4 / PARTS>(row, vv + p * (E / 4 / PARTS), lane);
                if (lane == 0) g_part[p * E + e] = acc;
            } else {
                int idx = t - n_attn;
                int blk = 1 + (idx >> 10);
                int e   = idx & (E - 1);
                const float4* wo  = (const float4*)(Wo + (size_t)blk * E * E + (size_t)e * E);
                const float4* wv2 = (const float4*)(Wv + (size_t)blk * E * NWA);
                float acc[NWA];
#pragma unroll
                for (int j = 0; j < NWA; j++) acc[j] = 0.f;
                for (int kk = lane; kk < E / 4; kk += 32) {   // kk -> k = 4kk..4kk+3
                    float4 w = wo[kk];
#pragma unroll
                    for (int kq = 0; kq < 4; kq++) {
                        float ws = (kq == 0) ? w.x : (kq == 1) ? w.y : (kq == 2) ? w.z : w.w;
                        float4 a0 = wv2[(4 * kk + kq) * 2];
                        float4 b0 = wv2[(4 * kk + kq) * 2 + 1];
                        acc[0] = fmaf(ws, a0.x, acc[0]);
                        acc[1] = fmaf(ws, a0.y, acc[1]);
                        acc[2] = fmaf(ws, a0.z, acc[2]);
                        acc[3] = fmaf(ws, a0.w, acc[3]);
                        acc[4] = fmaf(ws, b0.x, acc[4]);
                        acc[5] = fmaf(ws, b0.y, acc[5]);
                        acc[6] = fmaf(ws, b0.z, acc[6]);
                        acc[7] = fmaf(ws, b0.w, acc[7]);
                    }
                }
#pragma unroll
                for (int j = 0; j < NWA; j++) {
#pragma unroll
                    for (int o = 16; o; o >>= 1)
                        acc[j] += __shfl_xor_sync(0xffffffffu, acc[j], o);
                }
                if (lane == 0) {
                    float4* mrow = (float4*)(g_M + ((size_t)blk * E + e) * NWA);
                    mrow[0] = make_float4(acc[0], acc[1], acc[2], acc[3]);
                    mrow[1] = make_float4(acc[4], acc[5], acc[6], acc[7]);
                }
            }
        }
    }
    grid_sync(nb, b, base, ++phase);

    // ========================== MAIN CHAIN ===================================
    for (int blk = 0; blk < NBLK; blk++) {
        // ---- attn (local): blk==0 from g_part partials, else M_blk @ proj ----
        float attn_v;
        if (blk == 0) {
            attn_v = __ldcg(&g_part[0 * E + tid]) + __ldcg(&g_part[1 * E + tid])
                   + __ldcg(&g_part[2 * E + tid]) + __ldcg(&g_part[3 * E + tid]);
        } else {
            if (tid < NWA) m_s[tid] = cosf(h_s[tid] + phi_q[blk * NWA + tid]);
            __syncthreads();
            const float4* mrow = (const float4*)(g_M + ((size_t)blk * E + tid) * NWA);
            float4 a = __ldcg(&mrow[0]);
            float4 c = __ldcg(&mrow[1]);
            attn_v = a.x * m_s[0] + a.y * m_s[1] + a.z * m_s[2] + a.w * m_s[3]
                   + c.x * m_s[4] + c.y * m_s[5] + c.z * m_s[6] + c.w * m_s[7];
            __syncthreads();
        }

        // ---- h = LN1(h + attn)  (local, redundant per CTA) ----
        {
            float val = h_s[tid] + attn_v;
            float s1 = val, s2 = val * val;
#pragma unroll
            for (int o = 16; o; o >>= 1) {
                s1 += __shfl_xor_sync(0xffffffffu, s1, o);
                s2 += __shfl_xor_sync(0xffffffffu, s2, o);
            }
            if (lane == 0) { red1_s[wc] = s1; red2_s[wc] = s2; }
            __syncthreads();
            if (tid == 0) {
                float t1 = 0.f, t2 = 0.f;
#pragma unroll
                for (int i = 0; i < 32; i++) { t1 += red1_s[i]; t2 += red2_s[i]; }
                float mean = t1 * (1.0f / E);
                float var  = t2 * (1.0f / E) - mean * mean;
                stats[0] = mean;
                stats[1] = rsqrtf(fmaxf(var, 0.f) + 1e-5f);
            }
            __syncthreads();
            float nv = (val - stats[0]) * stats[1];
            h_s[tid] = nv * ln1_g[blk * E + tid] + ln1_b[blk * E + tid];
            __syncthreads();
        }

        // ---- r = relu(W1 @ m) (local, redundant) ----
        if (tid < NWF) m_s[tid] = cosf(h_s[tid]) * cosf(phi_f[blk * NWF + tid]);
        __syncthreads();
        {
            const float4* w1 = (const float4*)(W1 + (size_t)blk * FF * NWF);
            float m0 = m_s[0], m1 = m_s[1], m2 = m_s[2], m3 = m_s[3];
#pragma unroll
            for (int j = 0; j < FF / TPB; j++) {
                int ff = tid + j * TPB;
                float4 w = w1[ff];
                r_s[ff] = fmaxf(w.x * m0 + w.y * m1 + w.z * m2 + w.w * m3, 0.f);
            }
        }
        __syncthreads();

        // ---- f partials: 4 warps per row; E rows of len FF (16 MB stream) ----
        {
            const float4* rr = (const float4*)r_s;
            const float4* wbase = (const float4*)(W2 + (size_t)blk * E * FF);
            for (int t = gw; t < PARTS * E; t += wstride) {
                int e = t >> 2, p = t & 3;
                const float4* row = wbase + (size_t)e * (FF / 4) + p * (FF / 4 / PARTS);
                float acc = warp_dot_seg<FF / 4 / PARTS>(row, rr + p * (FF / 4 / PARTS), lane);
                if (lane == 0) g_part[p * E + e] = acc;
            }
        }
        grid_sync(nb, b, base, ++phase);

        // ---- h = LN2(h + f)  (local) ----
        {
            float val = h_s[tid]
                      + __ldcg(&g_part[0 * E + tid]) + __ldcg(&g_part[1 * E + tid])
                      + __ldcg(&g_part[2 * E + tid]) + __ldcg(&g_part[3 * E + tid]);
            float s1 = val, s2 = val * val;
#pragma unroll
            for (int o = 16; o; o >>= 1) {
                s1 += __shfl_xor_sync(0xffffffffu, s1, o);
                s2 += __shfl_xor_sync(0xffffffffu, s2, o);
            }
            if (lane == 0) { red1_s[wc] = s1; red2_s[wc] = s2; }
            __syncthreads();
            if (tid == 0) {
                float t1 = 0.f, t2 = 0.f;
#pragma unroll
                for (int i = 0; i < 32; i++) { t1 += red1_s[i]; t2 += red2_s[i]; }
                float mean = t1 * (1.0f / E);
                float var  = t2 * (1.0f / E) - mean * mean;
                stats[0] = mean;
                stats[1] = rsqrtf(fmaxf(var, 0.f) + 1e-5f);
            }
            __syncthreads();
            float nv = (val - stats[0]) * stats[1];
            h_s[tid] = nv * ln2_g[blk * E + tid] + ln2_b[blk * E + tid];
            __syncthreads();
        }
    }

    // ---- classifier partials: 4 warps per row; CC rows of len E ----
    {
        const float4* hh = (const float4*)h_s;
        for (int t = gw; t < PARTS * CC; t += wstride) {
            int c = t >> 2, p = t & 3;
            const float4* row = (const float4*)(Wc + (size_t)c * E) + p * (E / 4 / PARTS);
            float acc = warp_dot_seg<E / 4 / PARTS>(row, hh + p * (E / 4 / PARTS), lane);
            if (lane == 0) g_part[p * E + c] = acc;
        }
    }
    grid_sync(nb, b, base, ++phase);

    // ---- assemble classifier row (redundant per CTA), then broadcast ----
    if (tid < CC) {
        r_s[tid] = __ldcg(&g_part[0 * E + tid]) + __ldcg(&g_part[1 * E + tid])
                 + __ldcg(&g_part[2 * E + tid]) + __ldcg(&g_part[3 * E + tid]) + bc[tid];
    }
    __syncthreads();

    // warp-per-output-row broadcast: each warp writes one 4000B row
    {
        float4* out4 = (float4*)out;
        const float4* row4 = (const float4*)r_s;     // 250 float4
        for (int r = gw; r < BB; r += wstride) {
            float4* dst = out4 + (size_t)r * (CC / 4);
            for (int j = lane; j < CC / 4; j += 32) dst[j] = row4[j];
        }
    }
    // no trailing barrier and NO flag reset: flags are monotonic and the next
    // launch re-baselines from its own (uniform) flag value.
}

extern "C" void kernel_launch(void* const* d_in, const int* in_sizes, int n_in,
                              void* d_out, int out_size) {
    // metadata order: 0:x 1:Wq 2:Wk 3:Wv 4:Wo 5:phi_q 6:W1 7:W2 8:phi_f
    //                 9:ln1_g 10:ln1_b 11:ln2_g 12:ln2_b 13:Wc 14:bc
    const float* Wv    = (const float*)d_in[3];
    const float* Wo    = (const float*)d_in[4];
    const float* phi_q = (const float*)d_in[5];
    const float* W1    = (const float*)d_in[6];
    const float* W2    = (const float*)d_in[7];
    const float* phi_f = (const float*)d_in[8];
    const float* ln1_g = (const float*)d_in[9];
    const float* ln1_b = (const float*)d_in[10];
    const float* ln2_g = (const float*)d_in[11];
    const float* ln2_b = (const float*)d_in[12];
    const float* Wc    = (const float*)d_in[13];
    const float* bc    = (const float*)d_in[14];

    int dev = 0, sms = 0;
    cudaGetDevice(&dev);
    cudaDeviceGetAttribute(&sms, cudaDevAttrMultiProcessorCount, dev);
    if (sms <= 0) sms = 148;
    if (sms > MAXCTA) sms = MAXCTA;

    // Deadlock safety: software grid barrier requires every CTA resident.
    int blocksPerSM = 0;
    cudaOccupancyMaxActiveBlocksPerMultiprocessor(&blocksPerSM, hkt_kernel, TPB, 0);
    int grid = sms;
    if (blocksPerSM < 1) grid = 1;

    hkt_kernel<<<grid, TPB>>>(Wv, Wo, phi_q, W1, W2, phi_f,
                              ln1_g, ln1_b, ln2_g, ln2_b, Wc, bc,
                              (float*)d_out);
}

// round 6
// speedup vs baseline: 1.2779x; 1.2779x over previous
#include <cuda_runtime.h>
#include <cstdint>

// Problem constants (fixed by the reference)
#define E    1024
#define NBLK 6
#define FF   4096
#define CC   1000
#define BB   4096

// ---------------- device scratch (no allocations allowed) ----------------
__device__ float g_M[NBLK * E * 8];   // precomputed Wo@Wv per block (E x 8)
__device__ float g_f[2][E];           // f vector, double-buffered by block parity
__device__ float g_h1[2][E];          // h-after-LN1, double-buffered by block parity
__device__ float g_row[CC];           // classifier row

// ---------------- helpers ------------------------------------------------
__device__ __forceinline__ void cp16(void* smem, const void* gmem) {
    uint32_t s = (uint32_t)__cvta_generic_to_shared(smem);
    asm volatile("cp.async.cg.shared.global [%0], [%1], 16;" :: "r"(s), "l"(gmem));
}
__device__ __forceinline__ void cp_commit() {
    asm volatile("cp.async.commit_group;");
}
template<int N> __device__ __forceinline__ void cp_wait() {
    asm volatile("cp.async.wait_group %0;" :: "n"(N));
}
__device__ __forceinline__ float dot4(float4 a, float4 b) {
    return fmaf(a.x, b.x, fmaf(a.y, b.y, fmaf(a.z, b.z, a.w * b.w)));
}

// LayerNorm stats over E values (one per thread, 1024 threads).
// Leaves mean in stats[0], rstd in stats[1].
__device__ __forceinline__ void ln_stats(float val, float* red1, float* red2,
                                         float* stats, int lane, int wc) {
    float s1 = val, s2 = val * val;
#pragma unroll
    for (int o = 16; o; o >>= 1) {
        s1 += __shfl_xor_sync(0xffffffffu, s1, o);
        s2 += __shfl_xor_sync(0xffffffffu, s2, o);
    }
    if (lane == 0) { red1[wc] = s1; red2[wc] = s2; }
    __syncthreads();
    if (wc == 0) {
        float a = red1[lane], c = red2[lane];
#pragma unroll
        for (int o = 16; o; o >>= 1) {
            a += __shfl_xor_sync(0xffffffffu, a, o);
            c += __shfl_xor_sync(0xffffffffu, c, o);
        }
        if (lane == 0) {
            float mean = a * (1.0f / E);
            float var  = c * (1.0f / E) - mean * mean;
            stats[0] = mean;
            stats[1] = rsqrtf(fmaxf(var, 0.f) + 1e-5f);
        }
    }
    __syncthreads();
}

// ================= K_M: M_blk = Wo_blk @ Wv_blk  (E x 8 per block) =========
// grid = 192 CTAs x 256 threads: CTA c -> blk = c/32, rows (c%32)*32 .. +32.
// Wv block staged in SMEM; each warp computes 4 rows to amortize Wv reads.
__global__ void __launch_bounds__(256)
km_kernel(const float* __restrict__ Wo, const float* __restrict__ Wv)
{
    __shared__ __align__(16) float wv_s[E * 8];   // 32KB
    const int tid = threadIdx.x, lane = tid & 31, w = tid >> 5;
    const int blk  = blockIdx.x >> 5;
    const int row0 = (blockIdx.x & 31) * 32;

    const float4* wvg = (const float4*)(Wv + (size_t)blk * E * 8);
    float4* wv4 = (float4*)wv_s;
    for (int i = tid; i < E * 8 / 4; i += 256) wv4[i] = wvg[i];
    __syncthreads();

    const int r0 = row0 + 4 * w;                   // this warp's first row
    const float* wo0 = Wo + (size_t)blk * E * E + (size_t)r0 * E;

    float acc[4][8];
#pragma unroll
    for (int r = 0; r < 4; r++)
#pragma unroll
        for (int j = 0; j < 8; j++) acc[r][j] = 0.f;

#pragma unroll
    for (int kk = 0; kk < 8; kk++) {
        int k4 = lane + 32 * kk;                   // float4 index within row
        float4 wo4[4];
#pragma unroll
        for (int r = 0; r < 4; r++)
            wo4[r] = ((const float4*)(wo0 + (size_t)r * E))[k4];
#pragma unroll
        for (int q = 0; q < 4; q++) {
            int k = 4 * k4 + q;
            float4 a = wv4[2 * k], c = wv4[2 * k + 1];
#pragma unroll
            for (int r = 0; r < 4; r++) {
                float s = (q == 0) ? wo4[r].x : (q == 1) ? wo4[r].y
                        : (q == 2) ? wo4[r].z : wo4[r].w;
                acc[r][0] = fmaf(s, a.x, acc[r][0]);
                acc[r][1] = fmaf(s, a.y, acc[r][1]);
                acc[r][2] = fmaf(s, a.z, acc[r][2]);
                acc[r][3] = fmaf(s, a.w, acc[r][3]);
                acc[r][4] = fmaf(s, c.x, acc[r][4]);
                acc[r][5] = fmaf(s, c.y, acc[r][5]);
                acc[r][6] = fmaf(s, c.z, acc[r][6]);
                acc[r][7] = fmaf(s, c.w, acc[r][7]);
            }
        }
    }
#pragma unroll
    for (int r = 0; r < 4; r++) {
#pragma unroll
        for (int j = 0; j < 8; j++) {
#pragma unroll
            for (int o = 16; o; o >>= 1)
                acc[r][j] += __shfl_xor_sync(0xffffffffu, acc[r][j], o);
        }
        if (lane == 0) {
            float4* mrow = (float4*)(g_M + ((size_t)blk * E + r0 + r) * 8);
            mrow[0] = make_float4(acc[r][0], acc[r][1], acc[r][2], acc[r][3]);
            mrow[1] = make_float4(acc[r][4], acc[r][5], acc[r][6], acc[r][7]);
        }
    }
}

// ================= K_F(blk): one transformer block ==========================
// grid = 128 CTAs x 1024. CTA b owns W2 rows [8b, 8b+8) (128KB, cp.async-staged).
// Prologue (overlapped with the stream): LN2(prev) -> attn via M -> LN1 -> W1->r.
// Then dot staged rows with r and write final f values. g_f/g_h1 double-buffered.
__global__ void __launch_bounds__(1024)
kf_kernel(int blk,
          const float* __restrict__ W1,   const float* __restrict__ W2,
          const float* __restrict__ phi_q, const float* __restrict__ phi_f,
          const float* __restrict__ ln1_g, const float* __restrict__ ln1_b,
          const float* __restrict__ ln2_g, const float* __restrict__ ln2_b)
{
    extern __shared__ __align__(16) float stage[];        // 8 * FF floats = 128KB
    __shared__ __align__(16) float r_s[FF];
    __shared__ __align__(16) float h_s[E];
    __shared__ float red1[32], red2[32], stats[2], m_s[8];
    __shared__ float red_dot[8][8];

    const int tid = threadIdx.x, lane = tid & 31, wc = tid >> 5;
    const int b = blockIdx.x;
    const int cur = blk & 1, prev = (blk + 1) & 1;

    // ---- 1) issue the W2 slab stream immediately (fire-and-forget) ----
    {
        const float4* src = (const float4*)W2 + (size_t)blk * E * (FF / 4)
                          + (size_t)b * 8 * (FF / 4);
        float4* dst = (float4*)stage;
#pragma unroll
        for (int i = 0; i < 8; i++) {
            cp16(dst + i * 1024 + tid, src + i * 1024 + tid);
            if (i == 3 || i == 7) cp_commit();
        }
    }

    // ---- 2) prologue (overlaps the stream) ----
    float hp;
    if (blk == 0) {
        hp = 1.0f + (float)(tid & 1);                    // h0 = [1,2,1,2,...]
    } else {
        float val = g_h1[prev][tid] + g_f[prev][tid];
        ln_stats(val, red1, red2, stats, lane, wc);
        hp = (val - stats[0]) * stats[1] * ln2_g[(blk - 1) * E + tid]
           + ln2_b[(blk - 1) * E + tid];
    }
    h_s[tid] = hp;
    __syncthreads();
    if (tid < 8) m_s[tid] = cosf(h_s[tid] + phi_q[blk * 8 + tid]);
    __syncthreads();
    float attn;
    {
        const float4* mrow = (const float4*)(g_M + ((size_t)blk * E + tid) * 8);
        float4 a = mrow[0], c = mrow[1];
        attn = a.x * m_s[0] + a.y * m_s[1] + a.z * m_s[2] + a.w * m_s[3]
             + c.x * m_s[4] + c.y * m_s[5] + c.z * m_s[6] + c.w * m_s[7];
    }
    float h1;
    {
        float val = hp + attn;
        ln_stats(val, red1, red2, stats, lane, wc);
        h1 = (val - stats[0]) * stats[1] * ln1_g[blk * E + tid]
           + ln1_b[blk * E + tid];
    }
    if (b == 0) g_h1[cur][tid] = h1;                      // for next node
    h_s[tid] = h1;
    __syncthreads();
    if (tid < 4) m_s[tid] = cosf(h_s[tid]) * cosf(phi_f[blk * 4 + tid]);
    __syncthreads();
    {
        const float4* w1 = (const float4*)W1 + (size_t)blk * FF;  // FF rows x float4
        float m0 = m_s[0], m1 = m_s[1], m2 = m_s[2], m3 = m_s[3];
#pragma unroll
        for (int j = 0; j < FF / 1024; j++) {
            int ff = tid + j * 1024;
            float4 w = w1[ff];
            r_s[ff] = fmaxf(w.x * m0 + w.y * m1 + w.z * m2 + w.w * m3, 0.f);
        }
    }
    __syncthreads();

    // ---- 3) dot staged W2 rows with r ----
    const int rowin = wc >> 3;                 // 0..3 row within chunk
    const int seg   = wc & 7;                  // 0..7 segment of the row
    const float4* r4  = (const float4*)r_s;
    const float4* st4 = (const float4*)stage;
    float4 rr[4];
#pragma unroll
    for (int j = 0; j < 4; j++) rr[j] = r4[seg * 128 + lane + 32 * j];

    cp_wait<1>();              // rows 0..3 landed
    __syncthreads();
    {
        int rowg = rowin;
        float acc = 0.f;
#pragma unroll
        for (int j = 0; j < 4; j++)
            acc += dot4(st4[(size_t)rowg * 1024 + seg * 128 + lane + 32 * j], rr[j]);
#pragma unroll
        for (int o = 16; o; o >>= 1) acc += __shfl_xor_sync(0xffffffffu, acc, o);
        if (lane == 0) red_dot[rowg][seg] = acc;
    }
    cp_wait<0>();              // rows 4..7 landed
    __syncthreads();
    {
        int rowg = 4 + rowin;
        float acc = 0.f;
#pragma unroll
        for (int j = 0; j < 4; j++)
            acc += dot4(st4[(size_t)rowg * 1024 + seg * 128 + lane + 32 * j], rr[j]);
#pragma unroll
        for (int o = 16; o; o >>= 1) acc += __shfl_xor_sync(0xffffffffu, acc, o);
        if (lane == 0) red_dot[rowg][seg] = acc;
    }
    __syncthreads();
    if (tid < 8) {
        float s = 0.f;
#pragma unroll
        for (int p = 0; p < 8; p++) s += red_dot[tid][p];
        g_f[cur][b * 8 + tid] = s;
    }
}

// ================= K_CLS: LN2-final + classifier ===========================
// grid = 125 CTAs x 1024. CTA b owns Wc rows [8b, 8b+8) (32KB staged).
__global__ void __launch_bounds__(1024)
kcls_kernel(const float* __restrict__ Wc, const float* __restrict__ bc,
            const float* __restrict__ ln2_g, const float* __restrict__ ln2_b)
{
    extern __shared__ __align__(16) float cstage[];       // 8 * E floats = 32KB
    __shared__ __align__(16) float h_s[E];
    __shared__ float red1[32], red2[32], stats[2];
    __shared__ float red_cls[8][4];

    const int tid = threadIdx.x, lane = tid & 31, wc = tid >> 5;
    const int b = blockIdx.x;

    {
        const float4* src = (const float4*)Wc + (size_t)b * 8 * 256;  // row = 256 f4
        float4* dst = (float4*)cstage;
#pragma unroll
        for (int i = 0; i < 2; i++)
            cp16(dst + i * 1024 + tid, src + i * 1024 + tid);
        cp_commit();
    }

    // h_final = LN2 of block 5 (parity: 5&1 = 1)
    {
        float val = g_h1[1][tid] + g_f[1][tid];
        ln_stats(val, red1, red2, stats, lane, wc);
        h_s[tid] = (val - stats[0]) * stats[1] * ln2_g[5 * E + tid]
                 + ln2_b[5 * E + tid];
    }
    __syncthreads();

    cp_wait<0>();
    __syncthreads();

    const int r = wc >> 2, p = wc & 3;         // 8 rows x 4 warp-parts
    const float4* st4 = (const float4*)cstage;
    const float4* h4  = (const float4*)h_s;
    float acc = 0.f;
#pragma unroll
    for (int j = 0; j < 2; j++) {
        int idx = p * 64 + lane + 32 * j;
        acc += dot4(st4[r * 256 + idx], h4[idx]);
    }
#pragma unroll
    for (int o = 16; o; o >>= 1) acc += __shfl_xor_sync(0xffffffffu, acc, o);
    if (lane == 0) red_cls[r][p] = acc;
    __syncthreads();
    if (tid < 8) {
        float s = red_cls[tid][0] + red_cls[tid][1] + red_cls[tid][2] + red_cls[tid][3];
        g_row[b * 8 + tid] = s + bc[b * 8 + tid];
    }
}

// ================= K_BCAST: broadcast row to all B output rows =============
__global__ void __launch_bounds__(1024)
kb_kernel(float* __restrict__ out)
{
    __shared__ __align__(16) float row_s[CC];
    const int tid = threadIdx.x, lane = tid & 31;
    if (tid < CC) row_s[tid] = g_row[tid];
    __syncthreads();

    const int gwarp = blockIdx.x * 32 + (tid >> 5);
    const int nwarps = gridDim.x * 32;
    const float4* r4 = (const float4*)row_s;               // 250 float4
    for (int r = gwarp; r < BB; r += nwarps) {
        float4* dst = (float4*)out + (size_t)r * (CC / 4);
        for (int j = lane; j < CC / 4; j += 32) dst[j] = r4[j];
    }
}

// ================= host launch =============================================
extern "C" void kernel_launch(void* const* d_in, const int* in_sizes, int n_in,
                              void* d_out, int out_size) {
    // metadata order: 0:x 1:Wq 2:Wk 3:Wv 4:Wo 5:phi_q 6:W1 7:W2 8:phi_f
    //                 9:ln1_g 10:ln1_b 11:ln2_g 12:ln2_b 13:Wc 14:bc
    const float* Wv    = (const float*)d_in[3];
    const float* Wo    = (const float*)d_in[4];
    const float* phi_q = (const float*)d_in[5];
    const float* W1    = (const float*)d_in[6];
    const float* W2    = (const float*)d_in[7];
    const float* phi_f = (const float*)d_in[8];
    const float* ln1_g = (const float*)d_in[9];
    const float* ln1_b = (const float*)d_in[10];
    const float* ln2_g = (const float*)d_in[11];
    const float* ln2_b = (const float*)d_in[12];
    const float* Wc    = (const float*)d_in[13];
    const float* bc    = (const float*)d_in[14];

    static const int KF_DYN = 8 * FF * (int)sizeof(float);     // 128KB
    cudaFuncSetAttribute(kf_kernel, cudaFuncAttributeMaxDynamicSharedMemorySize, KF_DYN);

    km_kernel<<<192, 256>>>(Wo, Wv);
    for (int blk = 0; blk < NBLK; blk++)
        kf_kernel<<<128, 1024, KF_DYN>>>(blk, W1, W2, phi_q, phi_f,
                                         ln1_g, ln1_b, ln2_g, ln2_b);
    kcls_kernel<<<125, 1024, 8 * E * (int)sizeof(float)>>>(Wc, bc, ln2_g, ln2_b);
    kb_kernel<<<148, 1024>>>((float*)d_out);
}

// round 7
// speedup vs baseline: 1.3717x; 1.0734x over previous
#include <cuda_runtime.h>
#include <cstdint>

// Problem constants (fixed by the reference)
#define E    1024
#define NBLK 6
#define FF   4096
#define CC   1000
#define BB   4096

// ---------------- device scratch (no allocations allowed) ----------------
__device__ float g_M[NBLK * E * 8];   // precomputed Wo@Wv per block (E x 8)
__device__ float g_f[2][E];           // f vector, double-buffered by block parity
__device__ float g_h1[2][E];          // h-after-LN1, double-buffered by block parity
__device__ float g_row[CC];           // classifier row

__device__ __forceinline__ float dot4(float4 a, float4 b) {
    return fmaf(a.x, b.x, fmaf(a.y, b.y, fmaf(a.z, b.z, a.w * b.w)));
}

// LayerNorm stats over E values (one per thread, 1024 threads).
__device__ __forceinline__ void ln_stats(float val, float* red1, float* red2,
                                         float* stats, int lane, int wc) {
    float s1 = val, s2 = val * val;
#pragma unroll
    for (int o = 16; o; o >>= 1) {
        s1 += __shfl_xor_sync(0xffffffffu, s1, o);
        s2 += __shfl_xor_sync(0xffffffffu, s2, o);
    }
    if (lane == 0) { red1[wc] = s1; red2[wc] = s2; }
    __syncthreads();
    if (wc == 0) {
        float a = red1[lane], c = red2[lane];
#pragma unroll
        for (int o = 16; o; o >>= 1) {
            a += __shfl_xor_sync(0xffffffffu, a, o);
            c += __shfl_xor_sync(0xffffffffu, c, o);
        }
        if (lane == 0) {
            float mean = a * (1.0f / E);
            float var  = c * (1.0f / E) - mean * mean;
            stats[0] = mean;
            stats[1] = rsqrtf(fmaxf(var, 0.f) + 1e-5f);
        }
    }
    __syncthreads();
}

// ================= K_M: M_blk = Wo_blk @ Wv_blk  (E x 8 per block) =========
// grid = 192 CTAs x 256 threads: CTA c -> blk = c/32, rows (c%32)*32 .. +32.
__global__ void __launch_bounds__(256)
km_kernel(const float* __restrict__ Wo, const float* __restrict__ Wv)
{
    __shared__ __align__(16) float wv_s[E * 8];   // 32KB
    const int tid = threadIdx.x, lane = tid & 31, w = tid >> 5;
    const int blk  = blockIdx.x >> 5;
    const int row0 = (blockIdx.x & 31) * 32;

    const float4* wvg = (const float4*)(Wv + (size_t)blk * E * 8);
    float4* wv4 = (float4*)wv_s;
    for (int i = tid; i < E * 8 / 4; i += 256) wv4[i] = wvg[i];
    __syncthreads();

    const int r0 = row0 + 4 * w;
    const float* wo0 = Wo + (size_t)blk * E * E + (size_t)r0 * E;

    float acc[4][8];
#pragma unroll
    for (int r = 0; r < 4; r++)
#pragma unroll
        for (int j = 0; j < 8; j++) acc[r][j] = 0.f;

#pragma unroll
    for (int kk = 0; kk < 8; kk++) {
        int k4 = lane + 32 * kk;
        float4 wo4[4];
#pragma unroll
        for (int r = 0; r < 4; r++)
            wo4[r] = ((const float4*)(wo0 + (size_t)r * E))[k4];
#pragma unroll
        for (int q = 0; q < 4; q++) {
            int k = 4 * k4 + q;
            float4 a = wv4[2 * k], c = wv4[2 * k + 1];
#pragma unroll
            for (int r = 0; r < 4; r++) {
                float s = (q == 0) ? wo4[r].x : (q == 1) ? wo4[r].y
                        : (q == 2) ? wo4[r].z : wo4[r].w;
                acc[r][0] = fmaf(s, a.x, acc[r][0]);
                acc[r][1] = fmaf(s, a.y, acc[r][1]);
                acc[r][2] = fmaf(s, a.z, acc[r][2]);
                acc[r][3] = fmaf(s, a.w, acc[r][3]);
                acc[r][4] = fmaf(s, c.x, acc[r][4]);
                acc[r][5] = fmaf(s, c.y, acc[r][5]);
                acc[r][6] = fmaf(s, c.z, acc[r][6]);
                acc[r][7] = fmaf(s, c.w, acc[r][7]);
            }
        }
    }
#pragma unroll
    for (int r = 0; r < 4; r++) {
#pragma unroll
        for (int j = 0; j < 8; j++) {
#pragma unroll
            for (int o = 16; o; o >>= 1)
                acc[r][j] += __shfl_xor_sync(0xffffffffu, acc[r][j], o);
        }
        if (lane == 0) {
            float4* mrow = (float4*)(g_M + ((size_t)blk * E + r0 + r) * 8);
            mrow[0] = make_float4(acc[r][0], acc[r][1], acc[r][2], acc[r][3]);
            mrow[1] = make_float4(acc[r][4], acc[r][5], acc[r][6], acc[r][7]);
        }
    }
}

// ================= K_F(blk): one transformer block ==========================
// grid = 148 CTAs x 1024. CTA b owns W2 rows [7b, 7b+7) (112KB).
// W2 slice is loaded DIRECTLY INTO REGISTERS at kernel entry (8 float4/lane);
// the loads fly while the prologue (LN2(prev) -> attn via M -> LN1 -> W1 -> r)
// executes, then we FMA regs against r_s from SMEM. No cp.async (its 8cyc/SMSP
// issue rate caps streaming at ~1.8 TB/s chip-wide).
__global__ void __launch_bounds__(1024)
kf_kernel(int blk,
          const float* __restrict__ W1,   const float* __restrict__ W2,
          const float* __restrict__ phi_q, const float* __restrict__ phi_f,
          const float* __restrict__ ln1_g, const float* __restrict__ ln1_b,
          const float* __restrict__ ln2_g, const float* __restrict__ ln2_b)
{
    __shared__ __align__(16) float r_s[FF];
    __shared__ __align__(16) float h_s[E];
    __shared__ float red1[32], red2[32], stats[2], m_s[8];
    __shared__ float red_dot[7][4];

    const int tid = threadIdx.x, lane = tid & 31, wc = tid >> 5;
    const int b = blockIdx.x;
    const int cur = blk & 1, prev = (blk + 1) & 1;

    const int i = wc >> 2;                 // 0..7 row within CTA (7 valid)
    const int p = wc & 3;                  // 0..3 row segment
    const int row = b * 7 + i;
    const bool active = (i < 7) && (row < E);

    // ---- 1) issue the W2 row-slice loads into registers (fire-and-forget) ----
    float4 wreg[8];
    if (active) {
        const float4* src = (const float4*)W2 + (size_t)blk * E * (FF / 4)
                          + (size_t)row * (FF / 4) + p * 256 + lane;
#pragma unroll
        for (int j = 0; j < 8; j++) wreg[j] = src[32 * j];
    }

    // ---- 2) prologue (overlaps the in-flight loads) ----
    float hp;
    if (blk == 0) {
        hp = 1.0f + (float)(tid & 1);                    // h0 = [1,2,1,2,...]
    } else {
        float val = g_h1[prev][tid] + g_f[prev][tid];
        ln_stats(val, red1, red2, stats, lane, wc);
        hp = (val - stats[0]) * stats[1] * ln2_g[(blk - 1) * E + tid]
           + ln2_b[(blk - 1) * E + tid];
    }
    h_s[tid] = hp;
    __syncthreads();
    if (tid < 8) m_s[tid] = cosf(h_s[tid] + phi_q[blk * 8 + tid]);
    __syncthreads();
    float attn;
    {
        const float4* mrow = (const float4*)(g_M + ((size_t)blk * E + tid) * 8);
        float4 a = mrow[0], c = mrow[1];
        attn = a.x * m_s[0] + a.y * m_s[1] + a.z * m_s[2] + a.w * m_s[3]
             + c.x * m_s[4] + c.y * m_s[5] + c.z * m_s[6] + c.w * m_s[7];
    }
    float h1;
    {
        float val = hp + attn;
        ln_stats(val, red1, red2, stats, lane, wc);
        h1 = (val - stats[0]) * stats[1] * ln1_g[blk * E + tid]
           + ln1_b[blk * E + tid];
    }
    if (b == 0) g_h1[cur][tid] = h1;                      // for next node
    h_s[tid] = h1;
    __syncthreads();
    if (tid < 4) m_s[tid] = cosf(h_s[tid]) * cosf(phi_f[blk * 4 + tid]);
    __syncthreads();
    {
        const float4* w1 = (const float4*)W1 + (size_t)blk * FF;  // FF rows of float4
        float m0 = m_s[0], m1 = m_s[1], m2 = m_s[2], m3 = m_s[3];
#pragma unroll
        for (int j = 0; j < FF / 1024; j++) {
            int ff = tid + j * 1024;
            float4 w = w1[ff];
            r_s[ff] = fmaxf(w.x * m0 + w.y * m1 + w.z * m2 + w.w * m3, 0.f);
        }
    }
    __syncthreads();

    // ---- 3) dot register-resident W2 slice against r ----
    if (active) {
        const float4* r4 = (const float4*)r_s;
        float acc = 0.f;
#pragma unroll
        for (int j = 0; j < 8; j++)
            acc += dot4(wreg[j], r4[p * 256 + lane + 32 * j]);
#pragma unroll
        for (int o = 16; o; o >>= 1) acc += __shfl_xor_sync(0xffffffffu, acc, o);
        if (lane == 0) red_dot[i][p] = acc;
    }
    __syncthreads();
    if (tid < 7 && b * 7 + tid < E) {
        float s = red_dot[tid][0] + red_dot[tid][1] + red_dot[tid][2] + red_dot[tid][3];
        g_f[cur][b * 7 + tid] = s;
    }
}

// ================= K_CLS: LN2-final + classifier ===========================
// grid = 125 CTAs x 1024. CTA b owns Wc rows [8b, 8b+8); slice in registers.
__global__ void __launch_bounds__(1024)
kcls_kernel(const float* __restrict__ Wc, const float* __restrict__ bc,
            const float* __restrict__ ln2_g, const float* __restrict__ ln2_b)
{
    __shared__ __align__(16) float h_s[E];
    __shared__ float red1[32], red2[32], stats[2];
    __shared__ float red_cls[8][4];

    const int tid = threadIdx.x, lane = tid & 31, wc = tid >> 5;
    const int b = blockIdx.x;
    const int r = wc >> 2, p = wc & 3;         // 8 rows x 4 warp-parts

    // issue Wc loads into registers first
    float4 w0, w1;
    {
        const float4* src = (const float4*)Wc + ((size_t)b * 8 + r) * 256;
        w0 = src[p * 64 + lane];
        w1 = src[p * 64 + lane + 32];
    }

    // h_final = LN2 of block 5 (parity: 5&1 = 1)
    {
        float val = g_h1[1][tid] + g_f[1][tid];
        ln_stats(val, red1, red2, stats, lane, wc);
        h_s[tid] = (val - stats[0]) * stats[1] * ln2_g[5 * E + tid]
                 + ln2_b[5 * E + tid];
    }
    __syncthreads();

    const float4* h4 = (const float4*)h_s;
    float acc = dot4(w0, h4[p * 64 + lane]) + dot4(w1, h4[p * 64 + lane + 32]);
#pragma unroll
    for (int o = 16; o; o >>= 1) acc += __shfl_xor_sync(0xffffffffu, acc, o);
    if (lane == 0) red_cls[r][p] = acc;
    __syncthreads();
    if (tid < 8) {
        float s = red_cls[tid][0] + red_cls[tid][1] + red_cls[tid][2] + red_cls[tid][3];
        g_row[b * 8 + tid] = s + bc[b * 8 + tid];
    }
}

// ================= K_BCAST: broadcast row to all B output rows =============
__global__ void __launch_bounds__(1024)
kb_kernel(float* __restrict__ out)
{
    __shared__ __align__(16) float row_s[CC];
    const int tid = threadIdx.x, lane = tid & 31;
    if (tid < CC) row_s[tid] = g_row[tid];
    __syncthreads();

    const int gwarp = blockIdx.x * 32 + (tid >> 5);
    const int nwarps = gridDim.x * 32;
    const float4* r4 = (const float4*)row_s;               // 250 float4
    for (int r = gwarp; r < BB; r += nwarps) {
        float4* dst = (float4*)out + (size_t)r * (CC / 4);
        for (int j = lane; j < CC / 4; j += 32) dst[j] = r4[j];
    }
}

// ================= host launch =============================================
extern "C" void kernel_launch(void* const* d_in, const int* in_sizes, int n_in,
                              void* d_out, int out_size) {
    // metadata order: 0:x 1:Wq 2:Wk 3:Wv 4:Wo 5:phi_q 6:W1 7:W2 8:phi_f
    //                 9:ln1_g 10:ln1_b 11:ln2_g 12:ln2_b 13:Wc 14:bc
    const float* Wv    = (const float*)d_in[3];
    const float* Wo    = (const float*)d_in[4];
    const float* phi_q = (const float*)d_in[5];
    const float* W1    = (const float*)d_in[6];
    const float* W2    = (const float*)d_in[7];
    const float* phi_f = (const float*)d_in[8];
    const float* ln1_g = (const float*)d_in[9];
    const float* ln1_b = (const float*)d_in[10];
    const float* ln2_g = (const float*)d_in[11];
    const float* ln2_b = (const float*)d_in[12];
    const float* Wc    = (const float*)d_in[13];
    const float* bc    = (const float*)d_in[14];

    km_kernel<<<192, 256>>>(Wo, Wv);
    for (int blk = 0; blk < NBLK; blk++)
        kf_kernel<<<148, 1024>>>(blk, W1, W2, phi_q, phi_f,
                                 ln1_g, ln1_b, ln2_g, ln2_b);
    kcls_kernel<<<125, 1024>>>(Wc, bc, ln2_g, ln2_b);
    kb_kernel<<<148, 1024>>>((float*)d_out);
}